// round 6
// baseline (speedup 1.0000x reference)
#include <cuda_runtime.h>
#include <cuda_bf16.h>
#include <cstdint>
#include <cstddef>

#define NB   16
#define LSEQ 2048
#define QD   1024
#define KD   768
#define OD   1024
#define KPQ  (3*QD)    // 3072
#define KPK  (3*KD)    // 2304
#define KPS  (3*LSEQ)  // 6144

// ---------------- scratch (device globals) ----------------
__device__ __align__(1024) __nv_bfloat16 g_Aq[(size_t)NB*LSEQ*KPQ];
__device__ __align__(1024) __nv_bfloat16 g_Ak[(size_t)NB*LSEQ*KPK];
__device__ __align__(1024) __nv_bfloat16 g_Av[(size_t)NB*LSEQ*KPK];
__device__ __align__(1024) __nv_bfloat16 g_Bq[(size_t)OD*KPQ];
__device__ __align__(1024) __nv_bfloat16 g_Bk[(size_t)OD*KPK];
__device__ __align__(1024) __nv_bfloat16 g_Bv[(size_t)OD*KPK];
__device__ __align__(1024) __nv_bfloat16 g_qA[(size_t)NB*LSEQ*(3*OD)];
__device__ __align__(1024) __nv_bfloat16 g_kB[(size_t)NB*LSEQ*(3*OD)];
__device__ __align__(1024) __nv_bfloat16 g_vT[(size_t)NB*OD*KPS];
__device__ __align__(1024) float         g_s [(size_t)NB*LSEQ*LSEQ];
__device__ __align__(1024) __nv_bfloat16 g_p [(size_t)NB*LSEQ*KPS];

// ---------------- helpers ----------------
__device__ __forceinline__ uint32_t smem_u32(const void* p) {
    uint32_t a;
    asm("{ .reg .u64 t; cvta.to.shared.u64 t, %1; cvt.u32.u64 %0, t; }" : "=r"(a) : "l"(p));
    return a;
}
#define SWZ(x) ((x) ^ (((x) >> 3) & 0x70))

__device__ __forceinline__ void cp16(uint32_t s, const void* g) {
    asm volatile("cp.async.cg.shared.global [%0], [%1], 16;" :: "r"(s), "l"(g));
}
__device__ __forceinline__ void cp_commit() { asm volatile("cp.async.commit_group;" ::: "memory"); }
template<int N> __device__ __forceinline__ void cp_wait() {
    asm volatile("cp.async.wait_group %0;" :: "n"(N) : "memory");
}
#define LDSM_X4(r0, r1, r2, r3, addr) \
    asm volatile("ldmatrix.sync.aligned.m8n8.x4.shared.b16 {%0,%1,%2,%3}, [%4];" \
        : "=r"(r0), "=r"(r1), "=r"(r2), "=r"(r3) : "r"(addr))
#define MMA_BF16(d, a, b) \
    asm volatile("mma.sync.aligned.m16n8k16.row.col.f32.bf16.bf16.f32 " \
        "{%0,%1,%2,%3}, {%4,%5,%6,%7}, {%8,%9}, {%0,%1,%2,%3};" \
        : "+f"((d)[0]), "+f"((d)[1]), "+f"((d)[2]), "+f"((d)[3]) \
        : "r"((a)[0]), "r"((a)[1]), "r"((a)[2]), "r"((a)[3]), "r"((b)[0]), "r"((b)[1]))

__device__ __forceinline__ void split2(float v, __nv_bfloat16& hi, __nv_bfloat16& lo) {
    hi = __float2bfloat16(v);
    lo = __float2bfloat16(v - __bfloat162float(hi));
}

// epilogue variants
#define EPI_F32   0
#define EPI_PACKA 1
#define EPI_PACKB 2
#define EPI_VT    3

// ---------------------------------------------------------------------------
// HMMA GEMM: A:[M,K] bf16 K-major, B:[N,K] bf16 K-major.
// Tile 128x128x64, 256 threads, 3-stage cp.async pipeline with a SINGLE
// __syncthreads per k-chunk (loads for chunk i+2 go into the slot freed by
// chunk i-1, proven free by the barrier).  K % 64 == 0, K/64 >= 3.
// ---------------------------------------------------------------------------
#define GSMEM (1024 + 3*32768)
template<int EPI>
__global__ __launch_bounds__(256)
void mma_gemm(const __nv_bfloat16* __restrict__ A, const __nv_bfloat16* __restrict__ B,
              void* __restrict__ Cv, const float* __restrict__ bias,
              int K, size_t sA, size_t sB, size_t sC, int ldo, int seg, float scale)
{
    extern __shared__ char dsm[];
    const uint32_t raw  = smem_u32(dsm);
    const uint32_t STG  = (raw + 1023u) & ~1023u;

    const int tid  = threadIdx.x;
    const int wid  = tid >> 5;
    const int lane = tid & 31;
    const int wm   = wid & 3;
    const int wn   = wid >> 2;
    const int rowt = tid >> 3;
    const int segt = tid & 7;

    const __nv_bfloat16* Ab = A + blockIdx.z * sA + (size_t)(blockIdx.y * 128) * K;
    const __nv_bfloat16* Bb = B + blockIdx.z * sB + (size_t)(blockIdx.x * 128) * K;
    const int nk = K >> 6;

    auto loadChunk = [&](int c, int slot) {
        const uint32_t sb = STG + (uint32_t)slot * 32768u;
        const __nv_bfloat16* ag = Ab + (size_t)rowt * K + (size_t)c * 64 + segt * 8;
        const __nv_bfloat16* bg = Bb + (size_t)rowt * K + (size_t)c * 64 + segt * 8;
        #pragma unroll
        for (int j = 0; j < 4; j++) {
            uint32_t off = SWZ((uint32_t)((rowt + j * 32) * 128 + segt * 16));
            cp16(sb + off, ag + (size_t)j * 32 * K);
            cp16(sb + 16384u + off, bg + (size_t)j * 32 * K);
        }
    };
    // prologue: 2 of 3 stages in flight
    loadChunk(0, 0); cp_commit();
    loadChunk(1, 1); cp_commit();

    float acc[2][8][4];
    #pragma unroll
    for (int mf = 0; mf < 2; mf++)
        #pragma unroll
        for (int nf = 0; nf < 8; nf++)
            #pragma unroll
            for (int e = 0; e < 4; e++) acc[mf][nf][e] = 0.f;

    const int aRow = wm * 32 + (lane & 7) + ((lane >> 3) & 1) * 8;
    const int aCol = ((lane >> 4) & 1) * 16;
    const int bRow = wn * 64 + (lane & 7) + ((lane >> 4) & 1) * 8;
    const int bCol = ((lane >> 3) & 1) * 16;

    for (int i = 0; i < nk; ++i) {
        const int slot = i % 3;
        cp_wait<1>();            // chunk i resident
        __syncthreads();         // + all warps done with chunk i-1
        if (i + 2 < nk) loadChunk(i + 2, (i + 2) % 3);   // into slot freed by i-1
        cp_commit();

        const uint32_t aB = STG + (uint32_t)slot * 32768u;
        const uint32_t bB = aB + 16384u;
        #pragma unroll
        for (int kk = 0; kk < 4; kk++) {
            uint32_t a[2][4], b[8][2];
            #pragma unroll
            for (int mf = 0; mf < 2; mf++) {
                uint32_t ad = aB + SWZ((uint32_t)((aRow + mf * 16) * 128 + aCol + kk * 32));
                LDSM_X4(a[mf][0], a[mf][1], a[mf][2], a[mf][3], ad);
            }
            #pragma unroll
            for (int p = 0; p < 4; p++) {
                uint32_t bd = bB + SWZ((uint32_t)((bRow + p * 16) * 128 + bCol + kk * 32));
                LDSM_X4(b[2*p][0], b[2*p][1], b[2*p+1][0], b[2*p+1][1], bd);
            }
            #pragma unroll
            for (int mf = 0; mf < 2; mf++)
                #pragma unroll
                for (int nf = 0; nf < 8; nf++)
                    MMA_BF16(acc[mf][nf], a[mf], b[nf]);
        }
    }

    // ------------------------- epilogues -------------------------
    const int gid = lane >> 2, q4 = lane & 3;
    const int m0 = blockIdx.y * 128 + wm * 32;
    const int n0 = blockIdx.x * 128 + wn * 64;

    if (EPI == EPI_F32) {
        float* Cb = (float*)Cv + blockIdx.z * sC;
        #pragma unroll
        for (int mf = 0; mf < 2; mf++) {
            #pragma unroll
            for (int nf = 0; nf < 8; nf++) {
                const int n = n0 + nf * 8 + q4 * 2;
                const int mA = m0 + mf * 16 + gid;
                float2 v0 = { acc[mf][nf][0] * scale, acc[mf][nf][1] * scale };
                float2 v1 = { acc[mf][nf][2] * scale, acc[mf][nf][3] * scale };
                *(float2*)(Cb + (size_t)mA * ldo + n)       = v0;
                *(float2*)(Cb + (size_t)(mA + 8) * ldo + n) = v1;
            }
        }
    } else if (EPI == EPI_PACKA || EPI == EPI_PACKB) {
        __nv_bfloat16* Ob = (__nv_bfloat16*)Cv;
        #pragma unroll
        for (int mf = 0; mf < 2; mf++) {
            #pragma unroll
            for (int nf = 0; nf < 8; nf++) {
                const int n = n0 + nf * 8 + q4 * 2;
                const float bx = __ldg(bias + n), by = __ldg(bias + n + 1);
                #pragma unroll
                for (int h = 0; h < 2; h++) {
                    const int mA = m0 + mf * 16 + gid + h * 8;
                    float vx = acc[mf][nf][2*h]   + bx;
                    float vy = acc[mf][nf][2*h+1] + by;
                    __nv_bfloat16 hx, lx, hy, ly;
                    split2(vx, hx, lx); split2(vy, hy, ly);
                    __nv_bfloat16* base = Ob + (size_t)mA * ldo + n;
                    *(__nv_bfloat162*)(base) = {hx, hy};
                    if (EPI == EPI_PACKA) {
                        *(__nv_bfloat162*)(base + seg)   = {lx, ly};
                        *(__nv_bfloat162*)(base + 2*seg) = {hx, hy};
                    } else {
                        *(__nv_bfloat162*)(base + seg)   = {hx, hy};
                        *(__nv_bfloat162*)(base + 2*seg) = {lx, ly};
                    }
                }
            }
        }
    } else { // EPI_VT
        cp_wait<0>();
        __syncthreads();
        float* st = (float*)(dsm + (STG - raw)) + wid * (32 * 65);
        #pragma unroll
        for (int mf = 0; mf < 2; mf++) {
            #pragma unroll
            for (int nf = 0; nf < 8; nf++) {
                const int c = nf * 8 + q4 * 2;
                const int n = n0 + c;
                const float bx = __ldg(bias + n), by = __ldg(bias + n + 1);
                st[(mf*16 + gid)     * 65 + c]     = acc[mf][nf][0] + bx;
                st[(mf*16 + gid)     * 65 + c + 1] = acc[mf][nf][1] + by;
                st[(mf*16 + gid + 8) * 65 + c]     = acc[mf][nf][2] + bx;
                st[(mf*16 + gid + 8) * 65 + c + 1] = acc[mf][nf][3] + by;
            }
        }
        __syncwarp();
        __nv_bfloat16* vt = (__nv_bfloat16*)Cv;
        const int bidx = m0 >> 11;
        const int s    = m0 & 2047;
        #pragma unroll
        for (int cc = 0; cc < 2; cc++) {
            const int c = lane + cc * 32;
            const int o = n0 + c;
            __nv_bfloat16 hi[32], lo[32];
            #pragma unroll
            for (int r = 0; r < 32; r++) split2(st[r * 65 + c], hi[r], lo[r]);
            __nv_bfloat16* dst = vt + ((size_t)bidx * OD + o) * KPS + s;
            #pragma unroll
            for (int r = 0; r < 32; r += 2) {
                *(__nv_bfloat162*)(dst + r)        = {hi[r], hi[r+1]};
                *(__nv_bfloat162*)(dst + 2048 + r) = {hi[r], hi[r+1]};
                *(__nv_bfloat162*)(dst + 4096 + r) = {lo[r], lo[r+1]};
            }
        }
    }
}

// ---------------------------------------------------------------------------
template<bool APACK>
__global__ __launch_bounds__(256)
void pack_split(const float* __restrict__ in, __nv_bfloat16* __restrict__ out,
                int D, size_t total4)
{
    size_t i = (size_t)blockIdx.x * 256 + threadIdx.x;
    if (i >= total4) return;
    const int d4 = D >> 2;
    size_t r = i / d4;
    int c = (int)(i % d4) * 4;
    float4 x = *(const float4*)(in + r * D + c);
    __nv_bfloat16 h[4], l[4];
    split2(x.x, h[0], l[0]); split2(x.y, h[1], l[1]);
    split2(x.z, h[2], l[2]); split2(x.w, h[3], l[3]);
    __nv_bfloat16* o = out + r * (size_t)(3 * D) + c;
    *(__nv_bfloat162*)(o + 0) = {h[0], h[1]};
    *(__nv_bfloat162*)(o + 2) = {h[2], h[3]};
    __nv_bfloat16* o1 = o + D, * o2 = o + 2 * D;
    if (APACK) {
        *(__nv_bfloat162*)(o1 + 0) = {l[0], l[1]}; *(__nv_bfloat162*)(o1 + 2) = {l[2], l[3]};
        *(__nv_bfloat162*)(o2 + 0) = {h[0], h[1]}; *(__nv_bfloat162*)(o2 + 2) = {h[2], h[3]};
    } else {
        *(__nv_bfloat162*)(o1 + 0) = {h[0], h[1]}; *(__nv_bfloat162*)(o1 + 2) = {h[2], h[3]};
        *(__nv_bfloat162*)(o2 + 0) = {l[0], l[1]}; *(__nv_bfloat162*)(o2 + 2) = {l[2], l[3]};
    }
}

// ---------------------------------------------------------------------------
__global__ __launch_bounds__(256)
void softmax_pack(const float* __restrict__ S, __nv_bfloat16* __restrict__ P)
{
    const float* row = S + (size_t)blockIdx.x * LSEQ;
    __nv_bfloat16* prow = P + (size_t)blockIdx.x * KPS;
    const int tid = threadIdx.x, lane = tid & 31, warp = tid >> 5;
    const int b0 = tid * 8;
    float4 x0 = *(const float4*)(row + b0);
    float4 x1 = *(const float4*)(row + b0 + 4);
    float v[8] = {x0.x, x0.y, x0.z, x0.w, x1.x, x1.y, x1.z, x1.w};
    __shared__ float red[8];
    float mx = v[0];
    #pragma unroll
    for (int i = 1; i < 8; i++) mx = fmaxf(mx, v[i]);
    #pragma unroll
    for (int o = 16; o > 0; o >>= 1) mx = fmaxf(mx, __shfl_xor_sync(~0u, mx, o));
    if (lane == 0) red[warp] = mx;
    __syncthreads();
    float m = red[0];
    #pragma unroll
    for (int i = 1; i < 8; i++) m = fmaxf(m, red[i]);
    __syncthreads();
    float s = 0.f;
    #pragma unroll
    for (int i = 0; i < 8; i++) { v[i] = __expf(v[i] - m); s += v[i]; }
    #pragma unroll
    for (int o = 16; o > 0; o >>= 1) s += __shfl_xor_sync(~0u, s, o);
    if (lane == 0) red[warp] = s;
    __syncthreads();
    float tot = 0.f;
    #pragma unroll
    for (int i = 0; i < 8; i++) tot += red[i];
    float inv = 1.0f / tot;
    #pragma unroll
    for (int i = 0; i < 8; i += 2) {
        __nv_bfloat16 h0, l0, h1, l1;
        split2(v[i] * inv, h0, l0);
        split2(v[i + 1] * inv, h1, l1);
        *(__nv_bfloat162*)(prow + b0 + i)            = {h0, h1};
        *(__nv_bfloat162*)(prow + LSEQ + b0 + i)     = {l0, l1};
        *(__nv_bfloat162*)(prow + 2 * LSEQ + b0 + i) = {h0, h1};
    }
}

// ---------------------------------------------------------------------------
extern "C" void kernel_launch(void* const* d_in, const int* in_sizes, int n_in,
                              void* d_out, int out_size)
{
    const float* query = (const float*)d_in[0];
    const float* key   = (const float*)d_in[1];
    const float* value = (const float*)d_in[2];
    const float* Wq    = (const float*)d_in[3];
    const float* bq    = (const float*)d_in[4];
    const float* Wk    = (const float*)d_in[5];
    const float* bk    = (const float*)d_in[6];
    const float* Wv    = (const float*)d_in[7];
    const float* bv    = (const float*)d_in[8];
    float*       out   = (float*)d_out;

    __nv_bfloat16 *aq, *ak, *av, *bqp, *bkp, *bvp, *qA, *kB, *vT, *pP;
    float *s;
    cudaGetSymbolAddress((void**)&aq,  g_Aq);
    cudaGetSymbolAddress((void**)&ak,  g_Ak);
    cudaGetSymbolAddress((void**)&av,  g_Av);
    cudaGetSymbolAddress((void**)&bqp, g_Bq);
    cudaGetSymbolAddress((void**)&bkp, g_Bk);
    cudaGetSymbolAddress((void**)&bvp, g_Bv);
    cudaGetSymbolAddress((void**)&qA,  g_qA);
    cudaGetSymbolAddress((void**)&kB,  g_kB);
    cudaGetSymbolAddress((void**)&vT,  g_vT);
    cudaGetSymbolAddress((void**)&s,   g_s);
    cudaGetSymbolAddress((void**)&pP,  g_p);

    cudaFuncSetAttribute(mma_gemm<EPI_F32>,   cudaFuncAttributeMaxDynamicSharedMemorySize, GSMEM);
    cudaFuncSetAttribute(mma_gemm<EPI_PACKA>, cudaFuncAttributeMaxDynamicSharedMemorySize, GSMEM);
    cudaFuncSetAttribute(mma_gemm<EPI_PACKB>, cudaFuncAttributeMaxDynamicSharedMemorySize, GSMEM);
    cudaFuncSetAttribute(mma_gemm<EPI_VT>,    cudaFuncAttributeMaxDynamicSharedMemorySize, GSMEM);

    const int M = NB * LSEQ;  // 32768

    // 1) split-pack inputs and weights
    pack_split<true ><<<(M * QD / 4 + 255) / 256, 256>>>(query, aq, QD, (size_t)M * QD / 4);
    pack_split<true ><<<(M * KD / 4 + 255) / 256, 256>>>(key,   ak, KD, (size_t)M * KD / 4);
    pack_split<true ><<<(M * KD / 4 + 255) / 256, 256>>>(value, av, KD, (size_t)M * KD / 4);
    pack_split<false><<<(OD * QD / 4 + 255) / 256, 256>>>(Wq, bqp, QD, (size_t)OD * QD / 4);
    pack_split<false><<<(OD * KD / 4 + 255) / 256, 256>>>(Wk, bkp, KD, (size_t)OD * KD / 4);
    pack_split<false><<<(OD * KD / 4 + 255) / 256, 256>>>(Wv, bvp, KD, (size_t)OD * KD / 4);

    // 2) projections with fused pack epilogues
    mma_gemm<EPI_PACKA><<<dim3(OD/128, M/128, 1), 256, GSMEM>>>(
        aq, bqp, qA, bq, KPQ, 0, 0, 0, 3*OD, OD, 1.f);
    mma_gemm<EPI_PACKB><<<dim3(OD/128, M/128, 1), 256, GSMEM>>>(
        ak, bkp, kB, bk, KPK, 0, 0, 0, 3*OD, OD, 1.f);
    mma_gemm<EPI_VT><<<dim3(OD/128, M/128, 1), 256, GSMEM>>>(
        av, bvp, vT, bv, KPK, 0, 0, 0, 0, 0, 1.f);

    // 3) scores = (q k^T)/32, per batch
    mma_gemm<EPI_F32><<<dim3(LSEQ/128, LSEQ/128, NB), 256, GSMEM>>>(
        qA, kB, s, nullptr, 3*OD,
        (size_t)LSEQ*3*OD, (size_t)LSEQ*3*OD, (size_t)LSEQ*LSEQ, LSEQ, 0, 0.03125f);

    // 4) softmax + pack probs
    softmax_pack<<<NB * LSEQ, 256>>>(s, pP);

    // 5) out = probs @ v, per batch
    mma_gemm<EPI_F32><<<dim3(OD/128, LSEQ/128, NB), 256, GSMEM>>>(
        pP, vT, out, nullptr, KPS,
        (size_t)LSEQ*KPS, (size_t)OD*KPS, (size_t)LSEQ*OD, OD, 0, 1.f);
}